// round 12
// baseline (speedup 1.0000x reference)
#include <cuda_runtime.h>
#include <cstddef>

// Problem constants
#define T_STEPS   1024
#define CHUNK     64
#define NCHUNK    (T_STEPS / CHUNK)   // 16
#define HDIM      64
#define NCS       4                    // sequences per CTA
#define THREADS   128
#define BTOT      4096
#define SEQS      (2 * BTOT)           // 8192 (x1 then x2)
#define GRID1     (SEQS / NCS)         // 2048
#define HEAD_BLOCK 256

// Scratch for final hidden states (device global: no allocation in kernel_launch)
__device__ float g_hfin[SEQS * HDIM];

// ---- packed f32x2 helpers (FFMA2: 2 fp32 FMAs per issue) ----
__device__ __forceinline__ unsigned long long pk2(float lo, float hi) {
    unsigned long long r;
    asm("mov.b64 %0, {%1, %2};" : "=l"(r) : "f"(lo), "f"(hi));
    return r;
}
__device__ __forceinline__ unsigned long long ffma2(unsigned long long a,
                                                    unsigned long long b,
                                                    unsigned long long c) {
    unsigned long long d;
    asm("fma.rn.f32x2 %0, %1, %2, %3;" : "=l"(d) : "l"(a), "l"(b), "l"(c));
    return d;
}
__device__ __forceinline__ float hsum2(unsigned long long v) {
    float lo, hi;
    asm("mov.b64 {%0, %1}, %2;" : "=f"(lo), "=f"(hi) : "l"(v));
    return lo + hi;
}

// fast, accurate activations (rel err ~1e-7)
__device__ __forceinline__ float sigm(float x) {
    return __fdividef(1.0f, 1.0f + __expf(-x));
}
__device__ __forceinline__ float tanh_fast(float x) {
    float e = __expf(-2.0f * fabsf(x));
    float t = __fdividef(1.0f - e, 1.0f + e);
    return copysignf(t, x);
}

// ============================================================================
// GRU kernel, k-split version.
// CTA = 128 threads handles NCS=4 sequences.
//   u    = tid & 63  : hidden unit owned by this thread
//   half = tid >> 6  : which 32-wide k-slice of the dot product it computes
// Thread holds W_hh rows {u, u+64, u+128}, cols [half*32, half*32+32) in regs
// (96 regs -> 3 CTAs/SM occupancy). Each step: both halves compute partial
// dots for all 4 seqs; halves exchange partials via SMEM; half 0 finishes
// activations for seqs {0,1}, half 1 for seqs {2,3}. Two barriers/step.
// ============================================================================
__global__ void __launch_bounds__(THREADS, 3)
gru_kernel(const float* __restrict__ x1, const float* __restrict__ x2,
           const float* __restrict__ Wih, const float* __restrict__ Whh,
           const float* __restrict__ bih, const float* __restrict__ bhh)
{
    __shared__ __align__(16) float h_sh[2][NCS][HDIM];    // 2 KB
    __shared__ __align__(16) float x_sh[NCS][CHUNK * 3];  // 3 KB
    __shared__ float p_sh[NCS][3][HDIM];                  // 3 KB partial dots

    const int tid  = threadIdx.x;
    const int u    = tid & 63;
    const int half = tid >> 6;
    const int koff = half * 32;        // k-slice start

    // ---- register-resident half-row recurrent weights, f32x2 packed ----
    unsigned long long wr[16], wz[16], wn[16];
#pragma unroll
    for (int i = 0; i < 16; i++) {
        wr[i] = pk2(Whh[(u      ) * 64 + koff + 2 * i], Whh[(u      ) * 64 + koff + 2 * i + 1]);
        wz[i] = pk2(Whh[(u +  64) * 64 + koff + 2 * i], Whh[(u +  64) * 64 + koff + 2 * i + 1]);
        wn[i] = pk2(Whh[(u + 128) * 64 + koff + 2 * i], Whh[(u + 128) * 64 + koff + 2 * i + 1]);
    }
    // input-side weights (D = 3) + biases
    const float wir0 = Wih[(u      ) * 3 + 0], wir1 = Wih[(u      ) * 3 + 1], wir2 = Wih[(u      ) * 3 + 2];
    const float wiz0 = Wih[(u +  64) * 3 + 0], wiz1 = Wih[(u +  64) * 3 + 1], wiz2 = Wih[(u +  64) * 3 + 2];
    const float win0 = Wih[(u + 128) * 3 + 0], win1 = Wih[(u + 128) * 3 + 1], win2 = Wih[(u + 128) * 3 + 2];
    const float cr  = bih[u]       + bhh[u];
    const float cz  = bih[u + 64]  + bhh[u + 64];
    const float cxn = bih[u + 128];
    const float bhn = bhh[u + 128];

    // seqs this thread activates / sends partials for
    const int sa = half * 2;           // activates sa, sa+1
    const int so = (half ^ 1) * 2;     // sends partials for so, so+1

    float hreg[2];                     // h for activated seqs
    hreg[0] = 0.0f; hreg[1] = 0.0f;
    if (half == 0) {
#pragma unroll
        for (int s = 0; s < NCS; s++) h_sh[0][s][u] = 0.0f;
    }
    __syncthreads();

    int buf = 0;
    for (int tc = 0; tc < NCHUNK; tc++) {
        // ---- stage x chunk: NCS seqs x CHUNK steps x 3 floats, float4 coalesced ----
        for (int i = tid; i < NCS * (CHUNK * 3 / 4); i += THREADS) {
            const int q = i / 48;
            const int j = i - q * 48;
            const int g = blockIdx.x * NCS + q;
            const float* base = (g < BTOT)
                ? (x1 + (size_t)g * (T_STEPS * 3))
                : (x2 + (size_t)(g - BTOT) * (T_STEPS * 3));
            reinterpret_cast<float4*>(&x_sh[q][0])[j] =
                reinterpret_cast<const float4*>(base + tc * (CHUNK * 3))[j];
        }
        __syncthreads();

        for (int tl = 0; tl < CHUNK; tl++) {
            // ---- partial dots for all 4 sequences over this thread's k-slice ----
            unsigned long long ar[NCS], az[NCS], an[NCS];
#pragma unroll
            for (int s = 0; s < NCS; s++) {
                unsigned long long a0 = 0ull, a1 = 0ull, a2 = 0ull;
                const ulonglong2* hp =
                    reinterpret_cast<const ulonglong2*>(&h_sh[buf][s][koff]);
#pragma unroll
                for (int k = 0; k < 8; k++) {
                    const ulonglong2 h4 = hp[k];   // broadcast LDS.128
                    a0 = ffma2(wr[2 * k], h4.x, a0);
                    a1 = ffma2(wz[2 * k], h4.x, a1);
                    a2 = ffma2(wn[2 * k], h4.x, a2);
                    a0 = ffma2(wr[2 * k + 1], h4.y, a0);
                    a1 = ffma2(wz[2 * k + 1], h4.y, a1);
                    a2 = ffma2(wn[2 * k + 1], h4.y, a2);
                }
                ar[s] = a0; az[s] = a1; an[s] = a2;
            }

            // ---- exchange partials for the seqs the OTHER half activates ----
            p_sh[so    ][0][u] = hsum2(ar[so    ]);
            p_sh[so    ][1][u] = hsum2(az[so    ]);
            p_sh[so    ][2][u] = hsum2(an[so    ]);
            p_sh[so + 1][0][u] = hsum2(ar[so + 1]);
            p_sh[so + 1][1][u] = hsum2(az[so + 1]);
            p_sh[so + 1][2][u] = hsum2(an[so + 1]);
            __syncthreads();

            // ---- finish gates + activation for this half's 2 sequences ----
#pragma unroll
            for (int j = 0; j < 2; j++) {
                const int s = sa + j;
                const float dr = hsum2(ar[s]) + p_sh[s][0][u];
                const float dz = hsum2(az[s]) + p_sh[s][1][u];
                const float dn = hsum2(an[s]) + p_sh[s][2][u];

                const float xv0 = x_sh[s][tl * 3 + 0];
                const float xv1 = x_sh[s][tl * 3 + 1];
                const float xv2 = x_sh[s][tl * 3 + 2];
                const float xr = fmaf(xv2, wir2, fmaf(xv1, wir1, fmaf(xv0, wir0, cr)));
                const float xz = fmaf(xv2, wiz2, fmaf(xv1, wiz1, fmaf(xv0, wiz0, cz)));
                const float xn = fmaf(xv2, win2, fmaf(xv1, win1, fmaf(xv0, win0, cxn)));

                const float r = sigm(xr + dr);
                const float z = sigm(xz + dz);
                const float n = tanh_fast(xn + r * (dn + bhn));
                const float hnew = n + z * (hreg[j] - n);   // (1-z)n + z h
                hreg[j] = hnew;
                h_sh[buf ^ 1][s][u] = hnew;
            }
            buf ^= 1;
            __syncthreads();   // new h visible; p_sh free for next step
        }
    }

#pragma unroll
    for (int j = 0; j < 2; j++) {
        const int g = blockIdx.x * NCS + sa + j;
        g_hfin[(size_t)g * HDIM + u] = hreg[j];
    }
}

// ============================================================================
// Kernel 2: diff -> Linear(64,32) -> ReLU -> Linear(32,1) -> Sigmoid.
// One warp per batch element; W1 staged transposed in SMEM (conflict-free).
// ============================================================================
__global__ void __launch_bounds__(HEAD_BLOCK)
head_kernel(const float* __restrict__ W1, const float* __restrict__ b1,
            const float* __restrict__ W2, const float* __restrict__ b2,
            float* __restrict__ out)
{
    __shared__ float W1t[64 * 32];   // W1t[k*32 + r] = W1[r*64 + k]
    __shared__ float b1s[32], W2s[32];
    __shared__ float b2s;

    const int tid = threadIdx.x;
    for (int i = tid; i < 32 * 64; i += HEAD_BLOCK) {
        const int r = i >> 6, c = i & 63;
        W1t[c * 32 + r] = W1[i];
    }
    if (tid < 32) { b1s[tid] = b1[tid]; W2s[tid] = W2[tid]; }
    if (tid == 0) b2s = b2[0];
    __syncthreads();

    const int gw   = (blockIdx.x * HEAD_BLOCK + tid) >> 5;  // batch element
    const int lane = tid & 31;
    if (gw >= BTOT) return;

    const float* h1 = g_hfin + (size_t)gw * HDIM;
    const float* h2 = g_hfin + (size_t)(gw + BTOT) * HDIM;
    const float d0 = fabsf(h1[lane]      - h2[lane]);
    const float d1 = fabsf(h1[lane + 32] - h2[lane + 32]);

    float acc = b1s[lane];
#pragma unroll
    for (int k = 0; k < 32; k++) {
        const float dk = __shfl_sync(0xffffffffu, d0, k);
        acc = fmaf(dk, W1t[k * 32 + lane], acc);
    }
#pragma unroll
    for (int k = 0; k < 32; k++) {
        const float dk = __shfl_sync(0xffffffffu, d1, k);
        acc = fmaf(dk, W1t[(k + 32) * 32 + lane], acc);
    }
    const float hid = fmaxf(acc, 0.0f);
    float p = hid * W2s[lane];
#pragma unroll
    for (int off = 16; off; off >>= 1)
        p += __shfl_xor_sync(0xffffffffu, p, off);
    if (lane == 0) out[gw] = sigm(p + b2s);
}

// ============================================================================
// Launch (graph-capturable: kernel launches only, no allocs/syncs)
// Input order (metadata): x1, x2, W_ih, W_hh, b_ih, b_hh, W1, b1, W2, b2
// ============================================================================
extern "C" void kernel_launch(void* const* d_in, const int* in_sizes, int n_in,
                              void* d_out, int out_size)
{
    (void)in_sizes; (void)n_in; (void)out_size;
    const float* x1  = (const float*)d_in[0];
    const float* x2  = (const float*)d_in[1];
    const float* Wih = (const float*)d_in[2];
    const float* Whh = (const float*)d_in[3];
    const float* bih = (const float*)d_in[4];
    const float* bhh = (const float*)d_in[5];
    const float* W1  = (const float*)d_in[6];
    const float* b1  = (const float*)d_in[7];
    const float* W2  = (const float*)d_in[8];
    const float* b2  = (const float*)d_in[9];
    float* out = (float*)d_out;

    gru_kernel<<<GRID1, THREADS>>>(x1, x2, Wih, Whh, bih, bhh);
    head_kernel<<<(BTOT * 32) / HEAD_BLOCK, HEAD_BLOCK>>>(W1, b1, W2, b2, out);
}

// round 13
// speedup vs baseline: 1.2329x; 1.2329x over previous
#include <cuda_runtime.h>
#include <cstddef>

// Problem constants
#define T_STEPS   1024
#define CHUNK     64
#define NCHUNK    (T_STEPS / CHUNK)   // 16
#define HDIM      64
#define NSEQ      2                    // sequences per 64-thread group
#define GROUPS    2                    // groups per CTA
#define NCS       (NSEQ * GROUPS)      // sequences per CTA = 4
#define THREADS   (64 * GROUPS)        // 128
#define BTOT      4096
#define GRID1     (BTOT / 2)           // 2048: CTA b owns batch elems {2b, 2b+1}

// ---- packed f32x2 helpers (FFMA2: 2 fp32 FMAs per issue) ----
__device__ __forceinline__ unsigned long long pk2(float lo, float hi) {
    unsigned long long r;
    asm("mov.b64 %0, {%1, %2};" : "=l"(r) : "f"(lo), "f"(hi));
    return r;
}
__device__ __forceinline__ unsigned long long ffma2(unsigned long long a,
                                                    unsigned long long b,
                                                    unsigned long long c) {
    unsigned long long d;
    asm("fma.rn.f32x2 %0, %1, %2, %3;" : "=l"(d) : "l"(a), "l"(b), "l"(c));
    return d;
}
__device__ __forceinline__ float hsum2(unsigned long long v) {
    float lo, hi;
    asm("mov.b64 {%0, %1}, %2;" : "=f"(lo), "=f"(hi) : "l"(v));
    return lo + hi;
}

// fast activations with short dependency chains (rel err ~1e-7, fp32 MUFU path)
__device__ __forceinline__ float sigm(float x) {
    return __fdividef(1.0f, 1.0f + __expf(-x));
}
__device__ __forceinline__ float tanhv(float x) {
    // tanh(x) = 2/(1+exp(-2x)) - 1 ; exp overflow -> inf -> 0 - 1 = -1 (correct)
    return __fdividef(2.0f, 1.0f + __expf(-2.0f * x)) - 1.0f;
}

// ============================================================================
// Fused Siamese-GRU kernel. CTA b handles batch elems {2b, 2b+1}:
//   seq q=0,1 : x1 rows 2b, 2b+1    seq q=2,3 : x2 rows 2b, 2b+1
// 64-thread group g advances seqs {2g, 2g+1}; thread u owns W_hh rows
// {u, u+64, u+128} register-resident (f32x2 packed). h double-buffered in
// SMEM -> one __syncthreads per timestep. Head (diff->MLP->sigmoid) runs
// in-CTA at the end; no global scratch, single kernel launch.
// ============================================================================
__global__ void __launch_bounds__(THREADS, 2)
siamese_gru_kernel(const float* __restrict__ x1, const float* __restrict__ x2,
                   const float* __restrict__ Wih, const float* __restrict__ Whh,
                   const float* __restrict__ bih, const float* __restrict__ bhh,
                   const float* __restrict__ W1, const float* __restrict__ b1,
                   const float* __restrict__ W2, const float* __restrict__ b2,
                   float* __restrict__ out)
{
    __shared__ __align__(16) float h_sh[2][NCS][HDIM];       // 2 KB
    __shared__ __align__(16) float x_sh[NCS][CHUNK * 3];     // 3 KB
    __shared__ float d_sh[2][HDIM];                          // head scratch

    const int tid = threadIdx.x;
    const int u   = tid & 63;     // hidden unit owned by this thread
    const int grp = tid >> 6;     // group within CTA

    // ---- register-resident recurrent weights, packed (even k, odd k) ----
    unsigned long long wr[32], wz[32], wn[32];
#pragma unroll
    for (int i = 0; i < 32; i++) {
        wr[i] = pk2(Whh[(u      ) * 64 + 2 * i], Whh[(u      ) * 64 + 2 * i + 1]);
        wz[i] = pk2(Whh[(u +  64) * 64 + 2 * i], Whh[(u +  64) * 64 + 2 * i + 1]);
        wn[i] = pk2(Whh[(u + 128) * 64 + 2 * i], Whh[(u + 128) * 64 + 2 * i + 1]);
    }
    // input-side weights (D = 3)
    const float wir0 = Wih[(u      ) * 3 + 0], wir1 = Wih[(u      ) * 3 + 1], wir2 = Wih[(u      ) * 3 + 2];
    const float wiz0 = Wih[(u +  64) * 3 + 0], wiz1 = Wih[(u +  64) * 3 + 1], wiz2 = Wih[(u +  64) * 3 + 2];
    const float win0 = Wih[(u + 128) * 3 + 0], win1 = Wih[(u + 128) * 3 + 1], win2 = Wih[(u + 128) * 3 + 2];
    // biases: r,z fold b_ih+b_hh; n keeps them split (n = tanh(xn + r*(hn + bhn)))
    const float cr  = bih[u]       + bhh[u];
    const float cz  = bih[u + 64]  + bhh[u + 64];
    const float cxn = bih[u + 128];
    const float bhn = bhh[u + 128];

    float hreg[NSEQ];
#pragma unroll
    for (int s = 0; s < NSEQ; s++) {
        hreg[s] = 0.0f;
        h_sh[0][grp * NSEQ + s][u] = 0.0f;
    }
    __syncthreads();

    int buf = 0;
    for (int tc = 0; tc < NCHUNK; tc++) {
        // ---- stage x chunk: NCS seqs x CHUNK steps x 3 floats, float4 coalesced ----
        for (int i = tid; i < NCS * (CHUNK * 3 / 4); i += THREADS) {
            const int q = i / 48;
            const int j = i - q * 48;
            const float* base = (q < 2)
                ? (x1 + (size_t)(2 * blockIdx.x + q)     * (T_STEPS * 3))
                : (x2 + (size_t)(2 * blockIdx.x + q - 2) * (T_STEPS * 3));
            reinterpret_cast<float4*>(&x_sh[q][0])[j] =
                reinterpret_cast<const float4*>(base + tc * (CHUNK * 3))[j];
        }
        __syncthreads();

        for (int tl = 0; tl < CHUNK; tl++) {
#pragma unroll
            for (int s = 0; s < NSEQ; s++) {
                const int q = grp * NSEQ + s;
                const float xv0 = x_sh[q][tl * 3 + 0];
                const float xv1 = x_sh[q][tl * 3 + 1];
                const float xv2 = x_sh[q][tl * 3 + 2];
                float xr = fmaf(xv2, wir2, fmaf(xv1, wir1, fmaf(xv0, wir0, cr)));
                float xz = fmaf(xv2, wiz2, fmaf(xv1, wiz1, fmaf(xv0, wiz0, cz)));
                float xn = fmaf(xv2, win2, fmaf(xv1, win1, fmaf(xv0, win0, cxn)));

                unsigned long long ar = 0ull, az = 0ull, an = 0ull; // {+0,+0}
                const ulonglong2* hp =
                    reinterpret_cast<const ulonglong2*>(&h_sh[buf][q][0]);
#pragma unroll
                for (int k = 0; k < 16; k++) {
                    const ulonglong2 h4 = hp[k];       // broadcast LDS.128 (4 h values)
                    ar = ffma2(wr[2 * k], h4.x, ar);
                    az = ffma2(wz[2 * k], h4.x, az);
                    an = ffma2(wn[2 * k], h4.x, an);
                    ar = ffma2(wr[2 * k + 1], h4.y, ar);
                    az = ffma2(wz[2 * k + 1], h4.y, az);
                    an = ffma2(wn[2 * k + 1], h4.y, an);
                }
                const float r = sigm(xr + hsum2(ar));
                const float z = sigm(xz + hsum2(az));
                const float n = tanhv(xn + r * (hsum2(an) + bhn));
                const float hnew = n + z * (hreg[s] - n);   // (1-z)n + z h
                hreg[s] = hnew;
                h_sh[buf ^ 1][q][u] = hnew;
            }
            buf ^= 1;
            __syncthreads();   // new h visible; old buffer free for next step
        }
    }

    // ========================================================================
    // In-CTA head: diff -> Linear(64,32) -> ReLU -> Linear(32,1) -> Sigmoid.
    // Final h is in h_sh[buf][q][u]. h1 = q=elem, h2 = q=2+elem.
    // ========================================================================
    {
        const int e = grp;   // 128 threads cover (elem, unit) = (tid>>6, tid&63)
        d_sh[e][u] = fabsf(h_sh[buf][e][u] - h_sh[buf][2 + e][u]);
    }
    __syncthreads();

    if (tid < 64) {
        const int w    = tid >> 5;   // batch elem (warp 0 -> 2b, warp 1 -> 2b+1)
        const int r    = tid & 31;   // hidden-unit of the 32-wide MLP layer
        const float* w1r = W1 + r * 64;
        float acc = b1[r];
#pragma unroll 8
        for (int k = 0; k < 64; k++)
            acc = fmaf(d_sh[w][k], w1r[k], acc);
        const float hid = fmaxf(acc, 0.0f);
        float p = hid * W2[r];
#pragma unroll
        for (int off = 16; off; off >>= 1)
            p += __shfl_xor_sync(0xffffffffu, p, off);
        if (r == 0)
            out[2 * blockIdx.x + w] = sigm(p + b2[0]);
    }
}

// ============================================================================
// Launch (graph-capturable: single kernel launch, no allocs/syncs)
// Input order (metadata): x1, x2, W_ih, W_hh, b_ih, b_hh, W1, b1, W2, b2
// ============================================================================
extern "C" void kernel_launch(void* const* d_in, const int* in_sizes, int n_in,
                              void* d_out, int out_size)
{
    (void)in_sizes; (void)n_in; (void)out_size;
    const float* x1  = (const float*)d_in[0];
    const float* x2  = (const float*)d_in[1];
    const float* Wih = (const float*)d_in[2];
    const float* Whh = (const float*)d_in[3];
    const float* bih = (const float*)d_in[4];
    const float* bhh = (const float*)d_in[5];
    const float* W1  = (const float*)d_in[6];
    const float* b1  = (const float*)d_in[7];
    const float* W2  = (const float*)d_in[8];
    const float* b2  = (const float*)d_in[9];
    float* out = (float*)d_out;

    siamese_gru_kernel<<<GRID1, THREADS>>>(x1, x2, Wih, Whh, bih, bhh,
                                           W1, b1, W2, b2, out);
}